// round 1
// baseline (speedup 1.0000x reference)
#include <cuda_runtime.h>
#include <math.h>

#define Bc 8
#define Nn 2048
#define DFc 128
#define Ec 128
#define Hc 4

// ---------------- scratch (static device arrays; no allocation) ----------------
__device__ float g_g[Bc * Ec * DFc];                     // [b][e][d]  = sum_m W1[e,m] x[b,m,d]
__device__ float g_emb[Bc * Nn * Ec];                    // [b][n][e]
__device__ float g_q[(size_t)Bc * Hc * Nn * Ec];         // [b][h][n][f]
__device__ float g_v[(size_t)Bc * Hc * Nn * Ec];         // [b][h][n][f]
__device__ float g_u[Bc * Hc * DFc * Ec];                // [b][h][d][f] = sum_n x[b,n,d] v[b,h,n,f]
__device__ float g_r[(size_t)Bc * Hc * Nn * DFc];        // [b][h][n][d]
__device__ float g_h[(size_t)Bc * Nn * Hc * Ec];         // hcat layout [b][n][h][f]

// ---------------- zero init ----------------
__global__ void zero_kernel(float* p, int n) {
    int i = blockIdx.x * blockDim.x + threadIdx.x;
    if (i < n) p[i] = 0.0f;
}

// ---------------- reduce GEMM: C[128,128] += sum_m L[m,i] * R[m,j] ------------
// Split-K over m (grid.x chunks of 128), atomicAdd into C. Strided operand access.
__global__ __launch_bounds__(256) void reduce_gemm(
    const float* __restrict__ L, long l_sb, int l_div, int l_sm, int l_si,
    const float* __restrict__ R, long r_sb, int r_sm, int r_sj,
    float* __restrict__ C, long c_sb)
{
    __shared__ float Ls[32][132];
    __shared__ float Rs[32][132];

    int by = blockIdx.y;
    const float* Lb = L + (long)(by / l_div) * l_sb;
    const float* Rb = R + (long)by * r_sb;
    float* Cb = C + (long)by * c_sb;

    int t = threadIdx.x;
    int ti = t >> 4;        // 0..15 -> i = ti*8..
    int tj = t & 15;        // 0..15 -> j = tj*8..
    int m0 = blockIdx.x * 128;

    float acc[8][8];
#pragma unroll
    for (int a = 0; a < 8; a++)
#pragma unroll
        for (int b2 = 0; b2 < 8; b2++) acc[a][b2] = 0.0f;

    for (int ms = 0; ms < 128; ms += 32) {
        // load 32m x 128col tiles
#pragma unroll
        for (int e = 0; e < 16; e++) {
            int flat = e * 256 + t;
            int mm = flat >> 7;
            int col = flat & 127;
            Ls[mm][col] = Lb[(long)(m0 + ms + mm) * l_sm + (long)col * l_si];
            Rs[mm][col] = Rb[(long)(m0 + ms + mm) * r_sm + (long)col * r_sj];
        }
        __syncthreads();
#pragma unroll
        for (int mm = 0; mm < 32; mm++) {
            float4 l0 = *(const float4*)&Ls[mm][ti * 8];
            float4 l1 = *(const float4*)&Ls[mm][ti * 8 + 4];
            float4 r0 = *(const float4*)&Rs[mm][tj * 8];
            float4 r1 = *(const float4*)&Rs[mm][tj * 8 + 4];
            float lf[8] = {l0.x, l0.y, l0.z, l0.w, l1.x, l1.y, l1.z, l1.w};
            float rf[8] = {r0.x, r0.y, r0.z, r0.w, r1.x, r1.y, r1.z, r1.w};
#pragma unroll
            for (int a = 0; a < 8; a++)
#pragma unroll
                for (int b2 = 0; b2 < 8; b2++) acc[a][b2] += lf[a] * rf[b2];
        }
        __syncthreads();
    }
#pragma unroll
    for (int a = 0; a < 8; a++)
#pragma unroll
        for (int b2 = 0; b2 < 8; b2++)
            atomicAdd(&Cb[(ti * 8 + a) * 128 + tj * 8 + b2], acc[a][b2]);
}

// ---------------- generic Linear GEMM: C[M,128] = A[M,K] * Bm[128,K]^T + bias --
// A row-major (row stride K), Bm row-major (row stride K). M = 2048. act: 1=relu
__global__ __launch_bounds__(256) void gemm_mk_nk(
    const float* __restrict__ A, long a_sb, int a_div,
    const float* __restrict__ Bm, long b_sb, int b_mod,
    const float* __restrict__ bias, long bias_sb,
    float* __restrict__ C, long c_sb,
    int K, int act)
{
    __shared__ float As[32][68];     // [k][m]
    __shared__ float Bs[32][132];    // [k][n]

    int by = blockIdx.y;
    const float* Ab = A + (long)(by / a_div) * a_sb + (long)blockIdx.x * 64 * K;
    const float* Bb = Bm + (long)(by % b_mod) * b_sb;
    float* Cb = C + (long)by * c_sb + (long)blockIdx.x * 64 * 128;

    int t = threadIdx.x;
    int tm = t >> 4;    // 0..15 -> m = tm*4..
    int tn = t & 15;    // 0..15 -> n = tn*8..

    float acc[4][8];
#pragma unroll
    for (int a = 0; a < 4; a++)
#pragma unroll
        for (int b2 = 0; b2 < 8; b2++) acc[a][b2] = 0.0f;

    int ar = t >> 2;            // 0..63
    int akk = (t & 3) * 8;      // 0,8,16,24
    int br = t >> 1;            // 0..127
    int bkk = (t & 1) * 16;     // 0,16

    for (int k0 = 0; k0 < K; k0 += 32) {
        // A tile 64x32, transposed into [k][m]
        float4 a0 = *(const float4*)(Ab + (long)ar * K + k0 + akk);
        float4 a1 = *(const float4*)(Ab + (long)ar * K + k0 + akk + 4);
        As[akk + 0][ar] = a0.x; As[akk + 1][ar] = a0.y;
        As[akk + 2][ar] = a0.z; As[akk + 3][ar] = a0.w;
        As[akk + 4][ar] = a1.x; As[akk + 5][ar] = a1.y;
        As[akk + 6][ar] = a1.z; As[akk + 7][ar] = a1.w;
        // B tile 128x32, transposed into [k][n]
#pragma unroll
        for (int q4 = 0; q4 < 4; q4++) {
            float4 bvv = *(const float4*)(Bb + (long)br * K + k0 + bkk + q4 * 4);
            Bs[bkk + q4 * 4 + 0][br] = bvv.x;
            Bs[bkk + q4 * 4 + 1][br] = bvv.y;
            Bs[bkk + q4 * 4 + 2][br] = bvv.z;
            Bs[bkk + q4 * 4 + 3][br] = bvv.w;
        }
        __syncthreads();
#pragma unroll
        for (int kk = 0; kk < 32; kk++) {
            float4 av = *(const float4*)&As[kk][tm * 4];
            float4 b0 = *(const float4*)&Bs[kk][tn * 8];
            float4 b1 = *(const float4*)&Bs[kk][tn * 8 + 4];
            float af[4] = {av.x, av.y, av.z, av.w};
            float bf[8] = {b0.x, b0.y, b0.z, b0.w, b1.x, b1.y, b1.z, b1.w};
#pragma unroll
            for (int a = 0; a < 4; a++)
#pragma unroll
                for (int b2 = 0; b2 < 8; b2++) acc[a][b2] += af[a] * bf[b2];
        }
        __syncthreads();
    }

    float bv[8];
    if (bias) {
        const float* bp = bias + (long)(by % b_mod) * bias_sb;
#pragma unroll
        for (int j = 0; j < 8; j++) bv[j] = bp[tn * 8 + j];
    } else {
#pragma unroll
        for (int j = 0; j < 8; j++) bv[j] = 0.0f;
    }
#pragma unroll
    for (int a = 0; a < 4; a++) {
        float out[8];
#pragma unroll
        for (int j = 0; j < 8; j++) {
            float vv = acc[a][j] + bv[j];
            if (act == 1) vv = fmaxf(vv, 0.0f);
            out[j] = vv;
        }
        float* cp = Cb + (long)(tm * 4 + a) * 128 + tn * 8;
        *(float4*)cp = make_float4(out[0], out[1], out[2], out[3]);
        *(float4*)(cp + 4) = make_float4(out[4], out[5], out[6], out[7]);
    }
}

// ---------------- fused attention: h = tanh( (r x^T)/sqrt(E) ) v --------------
// per (b,h): r [N,128] as Q, x [N,128] as K, v [N,128] as V. No softmax.
// Block: 64 m-rows, loop p in tiles of 64. 256 threads.
#define ATTN_RS_OFF 0                       // rs [128][68]
#define ATTN_XS_OFF (128 * 68)              // xs [32][68]
#define ATTN_VS_OFF (ATTN_XS_OFF + 32 * 68) // vs [64][132]
#define ATTN_SS_OFF (ATTN_VS_OFF + 64 * 132)// Ss [64][68]
#define ATTN_SMEM_FLOATS (ATTN_SS_OFF + 64 * 68)

__global__ __launch_bounds__(256) void attn_kernel(
    const float* __restrict__ r, const float* __restrict__ x,
    const float* __restrict__ v, float* __restrict__ hcat)
{
    extern __shared__ float sm[];
    float* rs = sm + ATTN_RS_OFF;   // [k][m], stride 68
    float* xs = sm + ATTN_XS_OFF;   // [kk][p], stride 68
    float* vs = sm + ATTN_VS_OFF;   // [p][f], stride 132
    float* Ss = sm + ATTN_SS_OFF;   // [p][m], stride 68

    const float inv_scale = 0.08838834764831845f;  // 1/sqrt(128)

    int by = blockIdx.y;
    int b = by >> 2;
    int h = by & 3;
    int m0 = blockIdx.x * 64;

    const float* rb = r + (long)by * Nn * DFc;
    const float* xb = x + (long)b * Nn * DFc;
    const float* vb = v + (long)by * Nn * Ec;

    int t = threadIdx.x;
    int tm = t >> 4;    // 0..15
    int tp = t & 15;    // 0..15 (also used as tf for GEMM2)

    // load r tile [64 m][128 k], transposed into rs[k][m]
    {
        int mrow = t >> 2;
        int kk0 = (t & 3) * 32;
#pragma unroll
        for (int q4 = 0; q4 < 8; q4++) {
            float4 rv = *(const float4*)(rb + (long)(m0 + mrow) * DFc + kk0 + q4 * 4);
            rs[(kk0 + q4 * 4 + 0) * 68 + mrow] = rv.x;
            rs[(kk0 + q4 * 4 + 1) * 68 + mrow] = rv.y;
            rs[(kk0 + q4 * 4 + 2) * 68 + mrow] = rv.z;
            rs[(kk0 + q4 * 4 + 3) * 68 + mrow] = rv.w;
        }
    }

    float hacc[4][8];
#pragma unroll
    for (int a = 0; a < 4; a++)
#pragma unroll
        for (int j = 0; j < 8; j++) hacc[a][j] = 0.0f;

    for (int pt = 0; pt < Nn / 64; pt++) {
        int p0 = pt * 64;
        // load v tile [64 p][128 f] (natural layout, vectorized)
        {
            int vrow = t >> 2;
            int f0 = (t & 3) * 32;
#pragma unroll
            for (int q4 = 0; q4 < 8; q4++) {
                float4 vv = *(const float4*)(vb + (long)(p0 + vrow) * Ec + f0 + q4 * 4);
                *(float4*)&vs[vrow * 132 + f0 + q4 * 4] = vv;
            }
        }

        float sacc[4][4];
#pragma unroll
        for (int a = 0; a < 4; a++)
#pragma unroll
            for (int j = 0; j < 4; j++) sacc[a][j] = 0.0f;

        for (int kc = 0; kc < 4; kc++) {
            // load x chunk [32 kk][64 p] transposed
            {
                int prow = t >> 2;
                int xk0 = (t & 3) * 8;
                float4 x0 = *(const float4*)(xb + (long)(p0 + prow) * DFc + kc * 32 + xk0);
                float4 x1 = *(const float4*)(xb + (long)(p0 + prow) * DFc + kc * 32 + xk0 + 4);
                xs[(xk0 + 0) * 68 + prow] = x0.x; xs[(xk0 + 1) * 68 + prow] = x0.y;
                xs[(xk0 + 2) * 68 + prow] = x0.z; xs[(xk0 + 3) * 68 + prow] = x0.w;
                xs[(xk0 + 4) * 68 + prow] = x1.x; xs[(xk0 + 5) * 68 + prow] = x1.y;
                xs[(xk0 + 6) * 68 + prow] = x1.z; xs[(xk0 + 7) * 68 + prow] = x1.w;
            }
            __syncthreads();
#pragma unroll
            for (int kk = 0; kk < 32; kk++) {
                float4 rv = *(const float4*)&rs[(kc * 32 + kk) * 68 + tm * 4];
                float4 xv = *(const float4*)&xs[kk * 68 + tp * 4];
                float rf[4] = {rv.x, rv.y, rv.z, rv.w};
                float xf[4] = {xv.x, xv.y, xv.z, xv.w};
#pragma unroll
                for (int a = 0; a < 4; a++)
#pragma unroll
                    for (int j = 0; j < 4; j++) sacc[a][j] += rf[a] * xf[j];
            }
            __syncthreads();
        }

        // tanh epilogue -> Ss[p][m]
#pragma unroll
        for (int a = 0; a < 4; a++)
#pragma unroll
            for (int j = 0; j < 4; j++)
                Ss[(tp * 4 + j) * 68 + tm * 4 + a] = tanhf(sacc[a][j] * inv_scale);
        __syncthreads();

        // GEMM2: hacc += Ss^T (64m x 64p) * vs (64p x 128f)
#pragma unroll 8
        for (int pp = 0; pp < 64; pp++) {
            float4 sv = *(const float4*)&Ss[pp * 68 + tm * 4];
            float4 v0 = *(const float4*)&vs[pp * 132 + tp * 8];
            float4 v1 = *(const float4*)&vs[pp * 132 + tp * 8 + 4];
            float sf[4] = {sv.x, sv.y, sv.z, sv.w};
            float vf[8] = {v0.x, v0.y, v0.z, v0.w, v1.x, v1.y, v1.z, v1.w};
#pragma unroll
            for (int a = 0; a < 4; a++)
#pragma unroll
                for (int j = 0; j < 8; j++) hacc[a][j] += sf[a] * vf[j];
        }
        __syncthreads();
    }

    // write h into hcat [b][n][h][f]
#pragma unroll
    for (int a = 0; a < 4; a++) {
        int m = m0 + tm * 4 + a;
        float* hp = hcat + (((long)b * Nn + m) * Hc + h) * Ec + tp * 8;
        *(float4*)hp = make_float4(hacc[a][0], hacc[a][1], hacc[a][2], hacc[a][3]);
        *(float4*)(hp + 4) = make_float4(hacc[a][4], hacc[a][5], hacc[a][6], hacc[a][7]);
    }
}

// ---------------- launch ----------------
extern "C" void kernel_launch(void* const* d_in, const int* in_sizes, int n_in,
                              void* d_out, int out_size) {
    const float* x      = (const float*)d_in[0];   // [B,N,DF]
    const float* emb1_W = (const float*)d_in[1];   // [E,N]
    const float* emb1_b = (const float*)d_in[2];   // [E]
    const float* wq_W   = (const float*)d_in[3];   // [H,E,E]
    const float* wq_b   = (const float*)d_in[4];   // [H,E]
    // d_in[5], d_in[6]: wk_W, wk_b -- dead code in reference, skipped
    const float* wv_W   = (const float*)d_in[7];   // [H,E,E]
    const float* wv_b   = (const float*)d_in[8];   // [H,E]
    const float* emb2_W = (const float*)d_in[9];   // [E,H*E]
    const float* emb2_b = (const float*)d_in[10];  // [E]
    float* out = (float*)d_out;                    // [B,N,E]

    float *gg, *gemb, *gq, *gv, *gu, *gr, *gh;
    cudaGetSymbolAddress((void**)&gg, g_g);
    cudaGetSymbolAddress((void**)&gemb, g_emb);
    cudaGetSymbolAddress((void**)&gq, g_q);
    cudaGetSymbolAddress((void**)&gv, g_v);
    cudaGetSymbolAddress((void**)&gu, g_u);
    cudaGetSymbolAddress((void**)&gr, g_r);
    cudaGetSymbolAddress((void**)&gh, g_h);

    static int attn_smem_set = 0;
    if (!attn_smem_set) {
        cudaFuncSetAttribute(attn_kernel, cudaFuncAttributeMaxDynamicSharedMemorySize,
                             ATTN_SMEM_FLOATS * sizeof(float));
        attn_smem_set = 1;
    }

    // zero split-K accumulators
    zero_kernel<<<(Bc * Ec * DFc + 255) / 256, 256>>>(gg, Bc * Ec * DFc);
    zero_kernel<<<(Bc * Hc * DFc * Ec + 255) / 256, 256>>>(gu, Bc * Hc * DFc * Ec);

    // stage 1: g[b,e,d] = sum_m W1[e,m] x[b,m,d]
    reduce_gemm<<<dim3(16, Bc), 256>>>(emb1_W, 0, 1, 1, Nn,
                                       x, (long)Nn * DFc, DFc, 1,
                                       gg, (long)Ec * DFc);

    // stage 2: emb[b,n,e] = sum_d x[b,n,d] g[b,e,d] + emb1_b[e]
    gemm_mk_nk<<<dim3(32, Bc), 256>>>(x, (long)Nn * DFc, 1,
                                      gg, (long)Ec * DFc, Bc,
                                      emb1_b, 0,
                                      gemb, (long)Nn * Ec, DFc, 0);

    // stage 3: q, v projections per (b,h)
    gemm_mk_nk<<<dim3(32, Bc * Hc), 256>>>(gemb, (long)Nn * Ec, Hc,
                                           wq_W, (long)Ec * Ec, Hc,
                                           wq_b, Ec,
                                           gq, (long)Nn * Ec, Ec, 0);
    gemm_mk_nk<<<dim3(32, Bc * Hc), 256>>>(gemb, (long)Nn * Ec, Hc,
                                           wv_W, (long)Ec * Ec, Hc,
                                           wv_b, Ec,
                                           gv, (long)Nn * Ec, Ec, 0);

    // stage 4: u[b,h,d,f] = sum_n x[b,n,d] v[b,h,n,f]
    reduce_gemm<<<dim3(16, Bc * Hc), 256>>>(x, (long)Nn * DFc, Hc, DFc, 1,
                                            gv, (long)Nn * Ec, Ec, 1,
                                            gu, (long)DFc * Ec);

    // stage 5: r[b,h,n,d] = sum_f q[b,h,n,f] u[b,h,d,f]
    gemm_mk_nk<<<dim3(32, Bc * Hc), 256>>>(gq, (long)Nn * Ec, 1,
                                           gu, (long)DFc * Ec, Bc * Hc,
                                           nullptr, 0,
                                           gr, (long)Nn * DFc, Ec, 0);

    // stage 6: fused attention h = tanh(r x^T / sqrt(E)) v  -> hcat layout
    attn_kernel<<<dim3(Nn / 64, Bc * Hc), 256, ATTN_SMEM_FLOATS * sizeof(float)>>>(
        gr, x, gv, gh);

    // stage 7: out = relu(hcat @ emb2_W^T + emb2_b)
    gemm_mk_nk<<<dim3(32, Bc), 256>>>(gh, (long)Nn * Hc * Ec, 1,
                                      emb2_W, 0, Bc,
                                      emb2_b, 0,
                                      out, (long)Nn * Ec, Hc * Ec, 1);
}

// round 2
// speedup vs baseline: 1.4168x; 1.4168x over previous
#include <cuda_runtime.h>
#include <math.h>

#define Bc 8
#define Nn 2048
#define DFc 128
#define Ec 128
#define Hc 4

// ---------------- scratch (static device arrays; no allocation) ----------------
__device__ float g_g[Bc * Ec * DFc];                     // [b][e][d]
__device__ float g_emb[Bc * Nn * Ec];                    // [b][n][e]
__device__ float g_q[(size_t)Bc * Hc * Nn * Ec];         // [b][h][n][f]
__device__ float g_v[(size_t)Bc * Hc * Nn * Ec];         // [b][h][n][f]
__device__ float g_u[Bc * Hc * DFc * Ec];                // [b][h][d][f]
__device__ float g_r[(size_t)Bc * Hc * Nn * DFc];        // [b][h][n][d]
__device__ float g_h[(size_t)Bc * Nn * Hc * Ec];         // hcat layout [b][n][h][f]

// ---------------- zero init ----------------
__global__ void zero_kernel(float* p, int n) {
    int i = blockIdx.x * blockDim.x + threadIdx.x;
    if (i < n) p[i] = 0.0f;
}

// ---------------- reduce GEMM: C[128,128] += sum_m L[m,i] * R[m,j] ------------
__global__ __launch_bounds__(256) void reduce_gemm(
    const float* __restrict__ L, long l_sb, int l_div, int l_sm, int l_si,
    const float* __restrict__ R, long r_sb, int r_sm, int r_sj,
    float* __restrict__ C, long c_sb)
{
    __shared__ float Ls[32][132];
    __shared__ float Rs[32][132];

    int by = blockIdx.y;
    const float* Lb = L + (long)(by / l_div) * l_sb;
    const float* Rb = R + (long)by * r_sb;
    float* Cb = C + (long)by * c_sb;

    int t = threadIdx.x;
    int ti = t >> 4;
    int tj = t & 15;
    int m0 = blockIdx.x * 128;

    float acc[8][8];
#pragma unroll
    for (int a = 0; a < 8; a++)
#pragma unroll
        for (int b2 = 0; b2 < 8; b2++) acc[a][b2] = 0.0f;

    for (int ms = 0; ms < 128; ms += 32) {
#pragma unroll
        for (int e = 0; e < 16; e++) {
            int flat = e * 256 + t;
            int mm = flat >> 7;
            int col = flat & 127;
            Ls[mm][col] = Lb[(long)(m0 + ms + mm) * l_sm + (long)col * l_si];
            Rs[mm][col] = Rb[(long)(m0 + ms + mm) * r_sm + (long)col * r_sj];
        }
        __syncthreads();
#pragma unroll
        for (int mm = 0; mm < 32; mm++) {
            float4 l0 = *(const float4*)&Ls[mm][ti * 8];
            float4 l1 = *(const float4*)&Ls[mm][ti * 8 + 4];
            float4 r0 = *(const float4*)&Rs[mm][tj * 8];
            float4 r1 = *(const float4*)&Rs[mm][tj * 8 + 4];
            float lf[8] = {l0.x, l0.y, l0.z, l0.w, l1.x, l1.y, l1.z, l1.w};
            float rf[8] = {r0.x, r0.y, r0.z, r0.w, r1.x, r1.y, r1.z, r1.w};
#pragma unroll
            for (int a = 0; a < 8; a++)
#pragma unroll
                for (int b2 = 0; b2 < 8; b2++) acc[a][b2] += lf[a] * rf[b2];
        }
        __syncthreads();
    }
#pragma unroll
    for (int a = 0; a < 8; a++)
#pragma unroll
        for (int b2 = 0; b2 < 8; b2++)
            atomicAdd(&Cb[(ti * 8 + a) * 128 + tj * 8 + b2], acc[a][b2]);
}

// ---------------- generic Linear GEMM ----------------
__global__ __launch_bounds__(256) void gemm_mk_nk(
    const float* __restrict__ A, long a_sb, int a_div,
    const float* __restrict__ Bm, long b_sb, int b_mod,
    const float* __restrict__ bias, long bias_sb,
    float* __restrict__ C, long c_sb,
    int K, int act)
{
    __shared__ float As[32][68];
    __shared__ float Bs[32][132];

    int by = blockIdx.y;
    const float* Ab = A + (long)(by / a_div) * a_sb + (long)blockIdx.x * 64 * K;
    const float* Bb = Bm + (long)(by % b_mod) * b_sb;
    float* Cb = C + (long)by * c_sb + (long)blockIdx.x * 64 * 128;

    int t = threadIdx.x;
    int tm = t >> 4;
    int tn = t & 15;

    float acc[4][8];
#pragma unroll
    for (int a = 0; a < 4; a++)
#pragma unroll
        for (int b2 = 0; b2 < 8; b2++) acc[a][b2] = 0.0f;

    int ar = t >> 2;
    int akk = (t & 3) * 8;
    int br = t >> 1;
    int bkk = (t & 1) * 16;

    for (int k0 = 0; k0 < K; k0 += 32) {
        float4 a0 = *(const float4*)(Ab + (long)ar * K + k0 + akk);
        float4 a1 = *(const float4*)(Ab + (long)ar * K + k0 + akk + 4);
        As[akk + 0][ar] = a0.x; As[akk + 1][ar] = a0.y;
        As[akk + 2][ar] = a0.z; As[akk + 3][ar] = a0.w;
        As[akk + 4][ar] = a1.x; As[akk + 5][ar] = a1.y;
        As[akk + 6][ar] = a1.z; As[akk + 7][ar] = a1.w;
#pragma unroll
        for (int q4 = 0; q4 < 4; q4++) {
            float4 bvv = *(const float4*)(Bb + (long)br * K + k0 + bkk + q4 * 4);
            Bs[bkk + q4 * 4 + 0][br] = bvv.x;
            Bs[bkk + q4 * 4 + 1][br] = bvv.y;
            Bs[bkk + q4 * 4 + 2][br] = bvv.z;
            Bs[bkk + q4 * 4 + 3][br] = bvv.w;
        }
        __syncthreads();
#pragma unroll
        for (int kk = 0; kk < 32; kk++) {
            float4 av = *(const float4*)&As[kk][tm * 4];
            float4 b0 = *(const float4*)&Bs[kk][tn * 8];
            float4 b1 = *(const float4*)&Bs[kk][tn * 8 + 4];
            float af[4] = {av.x, av.y, av.z, av.w};
            float bf[8] = {b0.x, b0.y, b0.z, b0.w, b1.x, b1.y, b1.z, b1.w};
#pragma unroll
            for (int a = 0; a < 4; a++)
#pragma unroll
                for (int b2 = 0; b2 < 8; b2++) acc[a][b2] += af[a] * bf[b2];
        }
        __syncthreads();
    }

    float bv[8];
    if (bias) {
        const float* bp = bias + (long)(by % b_mod) * bias_sb;
#pragma unroll
        for (int j = 0; j < 8; j++) bv[j] = bp[tn * 8 + j];
    } else {
#pragma unroll
        for (int j = 0; j < 8; j++) bv[j] = 0.0f;
    }
#pragma unroll
    for (int a = 0; a < 4; a++) {
        float out[8];
#pragma unroll
        for (int j = 0; j < 8; j++) {
            float vv = acc[a][j] + bv[j];
            if (act == 1) vv = fmaxf(vv, 0.0f);
            out[j] = vv;
        }
        float* cp = Cb + (long)(tm * 4 + a) * 128 + tn * 8;
        *(float4*)cp = make_float4(out[0], out[1], out[2], out[3]);
        *(float4*)(cp + 4) = make_float4(out[4], out[5], out[6], out[7]);
    }
}

// ================= tensor-core fused attention =================
// h = tanh( (r x^T)/sqrt(E) ) v   per (b,h)
// Block: 128 m-rows, p-tiles of 64, f = 128 full. 256 threads (8 warps).
// S-gemm in 3xTF32 (fp32-accurate pre-tanh), GEMM2 attn(tf32) x v(hi+lo).

__device__ __forceinline__ unsigned f2tf(float f) {
    unsigned u;
    asm("cvt.rna.tf32.f32 %0, %1;" : "=r"(u) : "f"(f));
    return u;
}

__device__ __forceinline__ void mma_tf32(float c[4], const unsigned a[4], const unsigned b[2]) {
    asm volatile(
        "mma.sync.aligned.m16n8k8.row.col.f32.tf32.tf32.f32 "
        "{%0,%1,%2,%3}, {%4,%5,%6,%7}, {%8,%9}, {%0,%1,%2,%3};"
        : "+f"(c[0]), "+f"(c[1]), "+f"(c[2]), "+f"(c[3])
        : "r"(a[0]), "r"(a[1]), "r"(a[2]), "r"(a[3]), "r"(b[0]), "r"(b[1]));
}

__device__ __forceinline__ float tanh_fast(float x) {
    float y;
    asm("tanh.approx.f32 %0, %1;" : "=f"(y) : "f"(x));
    return y;
}

// smem layout (floats):
//   rs [128][132]               offset 0              (16896)
//   vs [64][132]                offset 16896          (8448)
//   xs [64][136] == Ss[128][68] offset 25344          (8704)
#define AT_RS 0
#define AT_VS 16896
#define AT_XS 25344
#define AT_SMEM_FLOATS (25344 + 8704)

__global__ __launch_bounds__(256) void attn_mma_kernel(
    const float* __restrict__ r, const float* __restrict__ x,
    const float* __restrict__ v, float* __restrict__ hcat)
{
    extern __shared__ float sm[];
    float* rs = sm + AT_RS;   // [m][k] stride 132
    float* vs = sm + AT_VS;   // [p][f] stride 132
    float* xs = sm + AT_XS;   // [p][k] stride 136
    float* Ss = sm + AT_XS;   // [m][p] stride 68  (aliases xs)

    const float inv_scale = 0.08838834764831845f;  // 1/sqrt(128)

    int by = blockIdx.y;
    int b = by >> 2;
    int h = by & 3;
    int m0 = blockIdx.x * 128;

    const float* rb = r + (long)by * Nn * DFc;
    const float* xb = x + (long)b * Nn * DFc;
    const float* vb = v + (long)by * Nn * Ec;

    int t = threadIdx.x;
    int warp = t >> 5;
    int lane = t & 31;
    int g = lane >> 2;      // groupID 0..7
    int q = lane & 3;       // thread-in-group 0..3

    int wm = warp >> 1;     // 0..3  -> m offset wm*32
    int wp = warp & 1;      // 0..1  -> p offset wp*32 (S-gemm)
    int wf = warp & 1;      // 0..1  -> f offset wf*64 (GEMM2)

    // load r tile [128 m][128 k] into rs (float4)
    {
        int row = t >> 1;
        int cb = (t & 1) * 64;
#pragma unroll
        for (int j = 0; j < 16; j++) {
            float4 rv = *(const float4*)(rb + (long)(m0 + row) * DFc + cb + j * 4);
            *(float4*)&rs[row * 132 + cb + j * 4] = rv;
        }
    }

    float hacc[2][8][4];
#pragma unroll
    for (int mt = 0; mt < 2; mt++)
#pragma unroll
        for (int nt = 0; nt < 8; nt++)
#pragma unroll
            for (int c = 0; c < 4; c++) hacc[mt][nt][c] = 0.0f;

    for (int pt = 0; pt < Nn / 64; pt++) {
        int p0 = pt * 64;
        __syncthreads();   // Ss (prev GEMM2 reads) done before overwriting xs; rs ready on first iter
        // load x tile [64 p][128 k] and v tile [64 p][128 f]
        {
            int row = t >> 2;
            int cb = (t & 3) * 32;
#pragma unroll
            for (int j = 0; j < 8; j++) {
                float4 xv = *(const float4*)(xb + (long)(p0 + row) * DFc + cb + j * 4);
                *(float4*)&xs[row * 136 + cb + j * 4] = xv;
                float4 vv = *(const float4*)(vb + (long)(p0 + row) * Ec + cb + j * 4);
                *(float4*)&vs[row * 132 + cb + j * 4] = vv;
            }
        }
        __syncthreads();

        // ---- S-gemm: 3xTF32, warp region m32 x p32 ----
        float sacc[2][4][4];
#pragma unroll
        for (int mt = 0; mt < 2; mt++)
#pragma unroll
            for (int nt = 0; nt < 4; nt++)
#pragma unroll
                for (int c = 0; c < 4; c++) sacc[mt][nt][c] = 0.0f;

#pragma unroll 4
        for (int kc = 0; kc < 16; kc++) {
            int k0 = kc * 8;
            unsigned a_hi[2][4], a_lo[2][4];
#pragma unroll
            for (int mt = 0; mt < 2; mt++) {
                int mr = wm * 32 + mt * 16;
                float e0 = rs[(mr + g) * 132 + k0 + q];
                float e1 = rs[(mr + g + 8) * 132 + k0 + q];
                float e2 = rs[(mr + g) * 132 + k0 + q + 4];
                float e3 = rs[(mr + g + 8) * 132 + k0 + q + 4];
                a_hi[mt][0] = f2tf(e0); a_lo[mt][0] = f2tf(e0 - __uint_as_float(a_hi[mt][0]));
                a_hi[mt][1] = f2tf(e1); a_lo[mt][1] = f2tf(e1 - __uint_as_float(a_hi[mt][1]));
                a_hi[mt][2] = f2tf(e2); a_lo[mt][2] = f2tf(e2 - __uint_as_float(a_hi[mt][2]));
                a_hi[mt][3] = f2tf(e3); a_lo[mt][3] = f2tf(e3 - __uint_as_float(a_hi[mt][3]));
            }
            unsigned b_hi[4][2], b_lo[4][2];
#pragma unroll
            for (int nt = 0; nt < 4; nt++) {
                int pr = wp * 32 + nt * 8 + g;
                float e0 = xs[pr * 136 + k0 + q];
                float e1 = xs[pr * 136 + k0 + q + 4];
                b_hi[nt][0] = f2tf(e0); b_lo[nt][0] = f2tf(e0 - __uint_as_float(b_hi[nt][0]));
                b_hi[nt][1] = f2tf(e1); b_lo[nt][1] = f2tf(e1 - __uint_as_float(b_hi[nt][1]));
            }
#pragma unroll
            for (int mt = 0; mt < 2; mt++)
#pragma unroll
                for (int nt = 0; nt < 4; nt++) {
                    mma_tf32(sacc[mt][nt], a_hi[mt], b_hi[nt]);
                    mma_tf32(sacc[mt][nt], a_hi[mt], b_lo[nt]);
                    mma_tf32(sacc[mt][nt], a_lo[mt], b_hi[nt]);
                }
        }
        __syncthreads();   // xs reads done before tanh overwrites (Ss aliases xs)

        // ---- tanh epilogue -> Ss[m][p] ----
#pragma unroll
        for (int mt = 0; mt < 2; mt++)
#pragma unroll
            for (int nt = 0; nt < 4; nt++) {
                int mrow = wm * 32 + mt * 16 + g;
                int pcol = wp * 32 + nt * 8 + 2 * q;
                Ss[mrow * 68 + pcol]           = tanh_fast(sacc[mt][nt][0] * inv_scale);
                Ss[mrow * 68 + pcol + 1]       = tanh_fast(sacc[mt][nt][1] * inv_scale);
                Ss[(mrow + 8) * 68 + pcol]     = tanh_fast(sacc[mt][nt][2] * inv_scale);
                Ss[(mrow + 8) * 68 + pcol + 1] = tanh_fast(sacc[mt][nt][3] * inv_scale);
            }
        __syncthreads();

        // ---- GEMM2: hacc += attn(tf32) * (v_hi + v_lo), warp region m32 x f64 ----
#pragma unroll 2
        for (int pc = 0; pc < 8; pc++) {
            int pk = pc * 8;
            unsigned a_f[2][4];
#pragma unroll
            for (int mt = 0; mt < 2; mt++) {
                int mr = wm * 32 + mt * 16;
                a_f[mt][0] = f2tf(Ss[(mr + g) * 68 + pk + q]);
                a_f[mt][1] = f2tf(Ss[(mr + g + 8) * 68 + pk + q]);
                a_f[mt][2] = f2tf(Ss[(mr + g) * 68 + pk + q + 4]);
                a_f[mt][3] = f2tf(Ss[(mr + g + 8) * 68 + pk + q + 4]);
            }
#pragma unroll
            for (int nt = 0; nt < 8; nt++) {
                int fc = wf * 64 + nt * 8 + g;
                float e0 = vs[(pk + q) * 132 + fc];
                float e1 = vs[(pk + q + 4) * 132 + fc];
                unsigned bh[2], bl[2];
                bh[0] = f2tf(e0); bl[0] = f2tf(e0 - __uint_as_float(bh[0]));
                bh[1] = f2tf(e1); bl[1] = f2tf(e1 - __uint_as_float(bh[1]));
#pragma unroll
                for (int mt = 0; mt < 2; mt++) {
                    mma_tf32(hacc[mt][nt], a_f[mt], bh);
                    mma_tf32(hacc[mt][nt], a_f[mt], bl);
                }
            }
        }
    }

    // write h into hcat [b][n][h][f]
#pragma unroll
    for (int mt = 0; mt < 2; mt++)
#pragma unroll
        for (int nt = 0; nt < 8; nt++) {
            int mrow = m0 + wm * 32 + mt * 16 + g;
            int fc = wf * 64 + nt * 8 + 2 * q;
            float* hp0 = hcat + (((long)b * Nn + mrow) * Hc + h) * Ec + fc;
            float* hp1 = hcat + (((long)b * Nn + mrow + 8) * Hc + h) * Ec + fc;
            *(float2*)hp0 = make_float2(hacc[mt][nt][0], hacc[mt][nt][1]);
            *(float2*)hp1 = make_float2(hacc[mt][nt][2], hacc[mt][nt][3]);
        }
}

// ---------------- launch ----------------
extern "C" void kernel_launch(void* const* d_in, const int* in_sizes, int n_in,
                              void* d_out, int out_size) {
    const float* x      = (const float*)d_in[0];
    const float* emb1_W = (const float*)d_in[1];
    const float* emb1_b = (const float*)d_in[2];
    const float* wq_W   = (const float*)d_in[3];
    const float* wq_b   = (const float*)d_in[4];
    const float* wv_W   = (const float*)d_in[7];
    const float* wv_b   = (const float*)d_in[8];
    const float* emb2_W = (const float*)d_in[9];
    const float* emb2_b = (const float*)d_in[10];
    float* out = (float*)d_out;

    float *gg, *gemb, *gq, *gv, *gu, *gr, *gh;
    cudaGetSymbolAddress((void**)&gg, g_g);
    cudaGetSymbolAddress((void**)&gemb, g_emb);
    cudaGetSymbolAddress((void**)&gq, g_q);
    cudaGetSymbolAddress((void**)&gv, g_v);
    cudaGetSymbolAddress((void**)&gu, g_u);
    cudaGetSymbolAddress((void**)&gr, g_r);
    cudaGetSymbolAddress((void**)&gh, g_h);

    static int attn_smem_set = 0;
    if (!attn_smem_set) {
        cudaFuncSetAttribute(attn_mma_kernel, cudaFuncAttributeMaxDynamicSharedMemorySize,
                             AT_SMEM_FLOATS * sizeof(float));
        attn_smem_set = 1;
    }

    zero_kernel<<<(Bc * Ec * DFc + 255) / 256, 256>>>(gg, Bc * Ec * DFc);
    zero_kernel<<<(Bc * Hc * DFc * Ec + 255) / 256, 256>>>(gu, Bc * Hc * DFc * Ec);

    // stage 1: g[b,e,d] = sum_m W1[e,m] x[b,m,d]
    reduce_gemm<<<dim3(16, Bc), 256>>>(emb1_W, 0, 1, 1, Nn,
                                       x, (long)Nn * DFc, DFc, 1,
                                       gg, (long)Ec * DFc);

    // stage 2: emb[b,n,e] = sum_d x[b,n,d] g[b,e,d] + emb1_b[e]
    gemm_mk_nk<<<dim3(32, Bc), 256>>>(x, (long)Nn * DFc, 1,
                                      gg, (long)Ec * DFc, Bc,
                                      emb1_b, 0,
                                      gemb, (long)Nn * Ec, DFc, 0);

    // stage 3: q, v projections per (b,h)
    gemm_mk_nk<<<dim3(32, Bc * Hc), 256>>>(gemb, (long)Nn * Ec, Hc,
                                           wq_W, (long)Ec * Ec, Hc,
                                           wq_b, Ec,
                                           gq, (long)Nn * Ec, Ec, 0);
    gemm_mk_nk<<<dim3(32, Bc * Hc), 256>>>(gemb, (long)Nn * Ec, Hc,
                                           wv_W, (long)Ec * Ec, Hc,
                                           wv_b, Ec,
                                           gv, (long)Nn * Ec, Ec, 0);

    // stage 4: u[b,h,d,f] = sum_n x[b,n,d] v[b,h,n,f]
    reduce_gemm<<<dim3(16, Bc * Hc), 256>>>(x, (long)Nn * DFc, Hc, DFc, 1,
                                            gv, (long)Nn * Ec, Ec, 1,
                                            gu, (long)DFc * Ec);

    // stage 5: r[b,h,n,d] = sum_f q[b,h,n,f] u[b,h,d,f]
    gemm_mk_nk<<<dim3(32, Bc * Hc), 256>>>(gq, (long)Nn * Ec, 1,
                                           gu, (long)DFc * Ec, Bc * Hc,
                                           nullptr, 0,
                                           gr, (long)Nn * DFc, Ec, 0);

    // stage 6: fused attention (tensor cores)
    attn_mma_kernel<<<dim3(Nn / 128, Bc * Hc), 256, AT_SMEM_FLOATS * sizeof(float)>>>(
        gr, x, gv, gh);

    // stage 7: out = relu(hcat @ emb2_W^T + emb2_b)
    gemm_mk_nk<<<dim3(32, Bc), 256>>>(gh, (long)Nn * Hc * Ec, 1,
                                      emb2_W, 0, Bc,
                                      emb2_b, 0,
                                      out, (long)Nn * Ec, Hc * Ec, 1);
}

// round 3
// speedup vs baseline: 1.5380x; 1.0855x over previous
#include <cuda_runtime.h>
#include <math.h>

#define Bc 8
#define Nn 2048
#define DFc 128
#define Ec 128
#define Hc 4

// ---------------- scratch (static device arrays; no allocation) ----------------
__device__ float g_g[Bc * Ec * DFc];                     // [b][e][d]
__device__ float g_emb[Bc * Nn * Ec];                    // [b][n][e]
__device__ float g_q[(size_t)Bc * Hc * Nn * Ec];         // [b][h][n][f]
__device__ float g_v[(size_t)Bc * Hc * Nn * Ec];         // [b][h][n][f]
__device__ float g_u[Bc * Hc * DFc * Ec];                // [b][h][d][f]
__device__ float g_r[(size_t)Bc * Hc * Nn * DFc];        // [b][h][n][d]
__device__ float g_h[(size_t)Bc * Nn * Hc * Ec];         // hcat layout [b][n][h][f]

// ---------------- zero init ----------------
__global__ void zero_kernel(float* p, int n) {
    int i = blockIdx.x * blockDim.x + threadIdx.x;
    if (i < n) p[i] = 0.0f;
}

// ---------------- tf32 helpers ----------------
__device__ __forceinline__ unsigned f2tf(float f) {
    unsigned u;
    asm("cvt.rna.tf32.f32 %0, %1;" : "=r"(u) : "f"(f));
    return u;
}

__device__ __forceinline__ void mma_tf32(float c[4], const unsigned a[4], const unsigned b[2]) {
    asm volatile(
        "mma.sync.aligned.m16n8k8.row.col.f32.tf32.tf32.f32 "
        "{%0,%1,%2,%3}, {%4,%5,%6,%7}, {%8,%9}, {%0,%1,%2,%3};"
        : "+f"(c[0]), "+f"(c[1]), "+f"(c[2]), "+f"(c[3])
        : "r"(a[0]), "r"(a[1]), "r"(a[2]), "r"(a[3]), "r"(b[0]), "r"(b[1]));
}

__device__ __forceinline__ float tanh_fast(float x) {
    float y;
    asm("tanh.approx.f32 %0, %1;" : "=f"(y) : "f"(x));
    return y;
}

// ================= unified 3xTF32 tensor GEMM =================
// C[M,N=128] = act( sum_k A[m,k] B[n,k] + bias[n] )
// A element: Ab[m*a_sm + k*a_sk], B element: Bb[n*b_sn + k*b_sk]
// grid = (M/128, nbatch, ksplit). ksplit>1 -> atomicAdd epilogue (no bias/act).
// CTA tile 128x128, K chunks of 32. 8 warps of 32m x 64n.
__global__ __launch_bounds__(256, 1) void tf32_gemm(
    const float* __restrict__ A, long a_sb, int a_div, int a_sm, int a_sk,
    const float* __restrict__ Bm, long b_sb, int b_mod, int b_sn, int b_sk,
    const float* __restrict__ bias, int bias_sb,
    float* __restrict__ C, long c_sb,
    int K, int ksplit, int act)
{
    __shared__ float As[128 * 36];
    __shared__ float Bs[128 * 36];

    int by = blockIdx.y;
    int m0 = blockIdx.x * 128;
    const float* Ab = A + (long)(by / a_div) * a_sb + (long)m0 * a_sm;
    const float* Bb = Bm + (long)(by % b_mod) * b_sb;
    float* Cb = C + (long)by * c_sb + (long)m0 * 128;

    int Kper = K / ksplit;
    int k0base = blockIdx.z * Kper;

    int t = threadIdx.x;
    int warp = t >> 5;
    int lane = t & 31;
    int g = lane >> 2;
    int q = lane & 3;
    int wm = warp >> 1;      // 0..3 -> m offset wm*32
    int wn = warp & 1;       // 0..1 -> n offset wn*64

    float acc[2][8][4];
#pragma unroll
    for (int mt = 0; mt < 2; mt++)
#pragma unroll
        for (int nt = 0; nt < 8; nt++)
#pragma unroll
            for (int c = 0; c < 4; c++) acc[mt][nt][c] = 0.0f;

    for (int kc0 = 0; kc0 < Kper; kc0 += 32) {
        int k0 = k0base + kc0;
        __syncthreads();
        // ---- load A tile [128 m][32 k] ----
        if (a_sk == 1) {
            int row = t >> 1;
            int c4 = (t & 1) * 16;
            const float* src = Ab + (long)row * a_sm + k0 + c4;
            float4 v0 = *(const float4*)(src);
            float4 v1 = *(const float4*)(src + 4);
            float4 v2 = *(const float4*)(src + 8);
            float4 v3 = *(const float4*)(src + 12);
            float* dst = &As[row * 36 + c4];
            *(float4*)(dst) = v0;
            *(float4*)(dst + 4) = v1;
            *(float4*)(dst + 8) = v2;
            *(float4*)(dst + 12) = v3;
        } else {
            int row = t & 127;
            int kb = (t >> 7) * 16;
#pragma unroll
            for (int e = 0; e < 16; e++)
                As[row * 36 + kb + e] = Ab[(long)row * a_sm + (long)(k0 + kb + e) * a_sk];
        }
        // ---- load B tile [128 n][32 k] ----
        if (b_sk == 1) {
            int row = t >> 1;
            int c4 = (t & 1) * 16;
            const float* src = Bb + (long)row * b_sn + k0 + c4;
            float4 v0 = *(const float4*)(src);
            float4 v1 = *(const float4*)(src + 4);
            float4 v2 = *(const float4*)(src + 8);
            float4 v3 = *(const float4*)(src + 12);
            float* dst = &Bs[row * 36 + c4];
            *(float4*)(dst) = v0;
            *(float4*)(dst + 4) = v1;
            *(float4*)(dst + 8) = v2;
            *(float4*)(dst + 12) = v3;
        } else {
            int row = t & 127;
            int kb = (t >> 7) * 16;
#pragma unroll
            for (int e = 0; e < 16; e++)
                Bs[row * 36 + kb + e] = Bb[(long)row * b_sn + (long)(k0 + kb + e) * b_sk];
        }
        __syncthreads();

        // ---- compute: 4 x k8 ----
#pragma unroll
        for (int kc = 0; kc < 4; kc++) {
            int k8 = kc * 8;
            unsigned ah[2][4], al[2][4];
#pragma unroll
            for (int mt = 0; mt < 2; mt++) {
                int mr = wm * 32 + mt * 16;
                float e0 = As[(mr + g) * 36 + k8 + q];
                float e1 = As[(mr + g + 8) * 36 + k8 + q];
                float e2 = As[(mr + g) * 36 + k8 + q + 4];
                float e3 = As[(mr + g + 8) * 36 + k8 + q + 4];
                ah[mt][0] = f2tf(e0); al[mt][0] = f2tf(e0 - __uint_as_float(ah[mt][0]));
                ah[mt][1] = f2tf(e1); al[mt][1] = f2tf(e1 - __uint_as_float(ah[mt][1]));
                ah[mt][2] = f2tf(e2); al[mt][2] = f2tf(e2 - __uint_as_float(ah[mt][2]));
                ah[mt][3] = f2tf(e3); al[mt][3] = f2tf(e3 - __uint_as_float(ah[mt][3]));
            }
            unsigned bh[8][2], bl[8][2];
#pragma unroll
            for (int nt = 0; nt < 8; nt++) {
                int nr = wn * 64 + nt * 8 + g;
                float e0 = Bs[nr * 36 + k8 + q];
                float e1 = Bs[nr * 36 + k8 + q + 4];
                bh[nt][0] = f2tf(e0); bl[nt][0] = f2tf(e0 - __uint_as_float(bh[nt][0]));
                bh[nt][1] = f2tf(e1); bl[nt][1] = f2tf(e1 - __uint_as_float(bh[nt][1]));
            }
#pragma unroll
            for (int mt = 0; mt < 2; mt++)
#pragma unroll
                for (int nt = 0; nt < 8; nt++) {
                    mma_tf32(acc[mt][nt], ah[mt], bh[nt]);
                    mma_tf32(acc[mt][nt], ah[mt], bl[nt]);
                    mma_tf32(acc[mt][nt], al[mt], bh[nt]);
                }
        }
    }

    // ---- epilogue ----
    if (ksplit > 1) {
#pragma unroll
        for (int mt = 0; mt < 2; mt++)
#pragma unroll
            for (int nt = 0; nt < 8; nt++) {
                int mr = wm * 32 + mt * 16 + g;
                int nc = wn * 64 + nt * 8 + 2 * q;
                atomicAdd(&Cb[(long)mr * 128 + nc], acc[mt][nt][0]);
                atomicAdd(&Cb[(long)mr * 128 + nc + 1], acc[mt][nt][1]);
                atomicAdd(&Cb[(long)(mr + 8) * 128 + nc], acc[mt][nt][2]);
                atomicAdd(&Cb[(long)(mr + 8) * 128 + nc + 1], acc[mt][nt][3]);
            }
    } else {
        const float* bp = bias ? (bias + (long)(by % b_mod) * bias_sb) : nullptr;
#pragma unroll
        for (int mt = 0; mt < 2; mt++)
#pragma unroll
            for (int nt = 0; nt < 8; nt++) {
                int mr = wm * 32 + mt * 16 + g;
                int nc = wn * 64 + nt * 8 + 2 * q;
                float b0 = bp ? bp[nc] : 0.0f;
                float b1 = bp ? bp[nc + 1] : 0.0f;
                float o00 = acc[mt][nt][0] + b0, o01 = acc[mt][nt][1] + b1;
                float o10 = acc[mt][nt][2] + b0, o11 = acc[mt][nt][3] + b1;
                if (act == 1) {
                    o00 = fmaxf(o00, 0.0f); o01 = fmaxf(o01, 0.0f);
                    o10 = fmaxf(o10, 0.0f); o11 = fmaxf(o11, 0.0f);
                }
                *(float2*)&Cb[(long)mr * 128 + nc] = make_float2(o00, o01);
                *(float2*)&Cb[(long)(mr + 8) * 128 + nc] = make_float2(o10, o11);
            }
    }
}

// ================= tensor-core fused attention (unchanged from R2) =================
#define AT_RS 0
#define AT_VS 16896
#define AT_XS 25344
#define AT_SMEM_FLOATS (25344 + 8704)

__global__ __launch_bounds__(256) void attn_mma_kernel(
    const float* __restrict__ r, const float* __restrict__ x,
    const float* __restrict__ v, float* __restrict__ hcat)
{
    extern __shared__ float sm[];
    float* rs = sm + AT_RS;   // [m][k] stride 132
    float* vs = sm + AT_VS;   // [p][f] stride 132
    float* xs = sm + AT_XS;   // [p][k] stride 136
    float* Ss = sm + AT_XS;   // [m][p] stride 68  (aliases xs)

    const float inv_scale = 0.08838834764831845f;  // 1/sqrt(128)

    int by = blockIdx.y;
    int b = by >> 2;
    int h = by & 3;
    int m0 = blockIdx.x * 128;

    const float* rb = r + (long)by * Nn * DFc;
    const float* xb = x + (long)b * Nn * DFc;
    const float* vb = v + (long)by * Nn * Ec;

    int t = threadIdx.x;
    int warp = t >> 5;
    int lane = t & 31;
    int g = lane >> 2;
    int q = lane & 3;

    int wm = warp >> 1;
    int wp = warp & 1;
    int wf = warp & 1;

    {
        int row = t >> 1;
        int cb = (t & 1) * 64;
#pragma unroll
        for (int j = 0; j < 16; j++) {
            float4 rv = *(const float4*)(rb + (long)(m0 + row) * DFc + cb + j * 4);
            *(float4*)&rs[row * 132 + cb + j * 4] = rv;
        }
    }

    float hacc[2][8][4];
#pragma unroll
    for (int mt = 0; mt < 2; mt++)
#pragma unroll
        for (int nt = 0; nt < 8; nt++)
#pragma unroll
            for (int c = 0; c < 4; c++) hacc[mt][nt][c] = 0.0f;

    for (int pt = 0; pt < Nn / 64; pt++) {
        int p0 = pt * 64;
        __syncthreads();
        {
            int row = t >> 2;
            int cb = (t & 3) * 32;
#pragma unroll
            for (int j = 0; j < 8; j++) {
                float4 xv = *(const float4*)(xb + (long)(p0 + row) * DFc + cb + j * 4);
                *(float4*)&xs[row * 136 + cb + j * 4] = xv;
                float4 vv = *(const float4*)(vb + (long)(p0 + row) * Ec + cb + j * 4);
                *(float4*)&vs[row * 132 + cb + j * 4] = vv;
            }
        }
        __syncthreads();

        float sacc[2][4][4];
#pragma unroll
        for (int mt = 0; mt < 2; mt++)
#pragma unroll
            for (int nt = 0; nt < 4; nt++)
#pragma unroll
                for (int c = 0; c < 4; c++) sacc[mt][nt][c] = 0.0f;

#pragma unroll 4
        for (int kc = 0; kc < 16; kc++) {
            int k0 = kc * 8;
            unsigned a_hi[2][4], a_lo[2][4];
#pragma unroll
            for (int mt = 0; mt < 2; mt++) {
                int mr = wm * 32 + mt * 16;
                float e0 = rs[(mr + g) * 132 + k0 + q];
                float e1 = rs[(mr + g + 8) * 132 + k0 + q];
                float e2 = rs[(mr + g) * 132 + k0 + q + 4];
                float e3 = rs[(mr + g + 8) * 132 + k0 + q + 4];
                a_hi[mt][0] = f2tf(e0); a_lo[mt][0] = f2tf(e0 - __uint_as_float(a_hi[mt][0]));
                a_hi[mt][1] = f2tf(e1); a_lo[mt][1] = f2tf(e1 - __uint_as_float(a_hi[mt][1]));
                a_hi[mt][2] = f2tf(e2); a_lo[mt][2] = f2tf(e2 - __uint_as_float(a_hi[mt][2]));
                a_hi[mt][3] = f2tf(e3); a_lo[mt][3] = f2tf(e3 - __uint_as_float(a_hi[mt][3]));
            }
            unsigned b_hi[4][2], b_lo[4][2];
#pragma unroll
            for (int nt = 0; nt < 4; nt++) {
                int pr = wp * 32 + nt * 8 + g;
                float e0 = xs[pr * 136 + k0 + q];
                float e1 = xs[pr * 136 + k0 + q + 4];
                b_hi[nt][0] = f2tf(e0); b_lo[nt][0] = f2tf(e0 - __uint_as_float(b_hi[nt][0]));
                b_hi[nt][1] = f2tf(e1); b_lo[nt][1] = f2tf(e1 - __uint_as_float(b_hi[nt][1]));
            }
#pragma unroll
            for (int mt = 0; mt < 2; mt++)
#pragma unroll
                for (int nt = 0; nt < 4; nt++) {
                    mma_tf32(sacc[mt][nt], a_hi[mt], b_hi[nt]);
                    mma_tf32(sacc[mt][nt], a_hi[mt], b_lo[nt]);
                    mma_tf32(sacc[mt][nt], a_lo[mt], b_hi[nt]);
                }
        }
        __syncthreads();

#pragma unroll
        for (int mt = 0; mt < 2; mt++)
#pragma unroll
            for (int nt = 0; nt < 4; nt++) {
                int mrow = wm * 32 + mt * 16 + g;
                int pcol = wp * 32 + nt * 8 + 2 * q;
                Ss[mrow * 68 + pcol]           = tanh_fast(sacc[mt][nt][0] * inv_scale);
                Ss[mrow * 68 + pcol + 1]       = tanh_fast(sacc[mt][nt][1] * inv_scale);
                Ss[(mrow + 8) * 68 + pcol]     = tanh_fast(sacc[mt][nt][2] * inv_scale);
                Ss[(mrow + 8) * 68 + pcol + 1] = tanh_fast(sacc[mt][nt][3] * inv_scale);
            }
        __syncthreads();

#pragma unroll 2
        for (int pc = 0; pc < 8; pc++) {
            int pk = pc * 8;
            unsigned a_f[2][4];
#pragma unroll
            for (int mt = 0; mt < 2; mt++) {
                int mr = wm * 32 + mt * 16;
                a_f[mt][0] = f2tf(Ss[(mr + g) * 68 + pk + q]);
                a_f[mt][1] = f2tf(Ss[(mr + g + 8) * 68 + pk + q]);
                a_f[mt][2] = f2tf(Ss[(mr + g) * 68 + pk + q + 4]);
                a_f[mt][3] = f2tf(Ss[(mr + g + 8) * 68 + pk + q + 4]);
            }
#pragma unroll
            for (int nt = 0; nt < 8; nt++) {
                int fc = wf * 64 + nt * 8 + g;
                float e0 = vs[(pk + q) * 132 + fc];
                float e1 = vs[(pk + q + 4) * 132 + fc];
                unsigned bh[2], bl[2];
                bh[0] = f2tf(e0); bl[0] = f2tf(e0 - __uint_as_float(bh[0]));
                bh[1] = f2tf(e1); bl[1] = f2tf(e1 - __uint_as_float(bh[1]));
#pragma unroll
                for (int mt = 0; mt < 2; mt++) {
                    mma_tf32(hacc[mt][nt], a_f[mt], bh);
                    mma_tf32(hacc[mt][nt], a_f[mt], bl);
                }
            }
        }
    }

#pragma unroll
    for (int mt = 0; mt < 2; mt++)
#pragma unroll
        for (int nt = 0; nt < 8; nt++) {
            int mrow = m0 + wm * 32 + mt * 16 + g;
            int fc = wf * 64 + nt * 8 + 2 * q;
            float* hp0 = hcat + (((long)b * Nn + mrow) * Hc + h) * Ec + fc;
            float* hp1 = hcat + (((long)b * Nn + mrow + 8) * Hc + h) * Ec + fc;
            *(float2*)hp0 = make_float2(hacc[mt][nt][0], hacc[mt][nt][1]);
            *(float2*)hp1 = make_float2(hacc[mt][nt][2], hacc[mt][nt][3]);
        }
}

// ---------------- launch ----------------
extern "C" void kernel_launch(void* const* d_in, const int* in_sizes, int n_in,
                              void* d_out, int out_size) {
    const float* x      = (const float*)d_in[0];
    const float* emb1_W = (const float*)d_in[1];
    const float* emb1_b = (const float*)d_in[2];
    const float* wq_W   = (const float*)d_in[3];
    const float* wq_b   = (const float*)d_in[4];
    const float* wv_W   = (const float*)d_in[7];
    const float* wv_b   = (const float*)d_in[8];
    const float* emb2_W = (const float*)d_in[9];
    const float* emb2_b = (const float*)d_in[10];
    float* out = (float*)d_out;

    float *gg, *gemb, *gq, *gv, *gu, *gr, *gh;
    cudaGetSymbolAddress((void**)&gg, g_g);
    cudaGetSymbolAddress((void**)&gemb, g_emb);
    cudaGetSymbolAddress((void**)&gq, g_q);
    cudaGetSymbolAddress((void**)&gv, g_v);
    cudaGetSymbolAddress((void**)&gu, g_u);
    cudaGetSymbolAddress((void**)&gr, g_r);
    cudaGetSymbolAddress((void**)&gh, g_h);

    static int attn_smem_set = 0;
    if (!attn_smem_set) {
        cudaFuncSetAttribute(attn_mma_kernel, cudaFuncAttributeMaxDynamicSharedMemorySize,
                             AT_SMEM_FLOATS * sizeof(float));
        attn_smem_set = 1;
    }

    // zero split-K accumulators
    zero_kernel<<<(Bc * Ec * DFc + 255) / 256, 256>>>(gg, Bc * Ec * DFc);
    zero_kernel<<<(Bc * Hc * DFc * Ec + 255) / 256, 256>>>(gu, Bc * Hc * DFc * Ec);

    // stage 1: g[b,e,d] = sum_m W1[e,m] x[b,m,d]   (split-K 8, atomic)
    tf32_gemm<<<dim3(1, Bc, 8), 256>>>(emb1_W, 0, Bc, Nn, 1,
                                       x, (long)Nn * DFc, Bc, 1, DFc,
                                       nullptr, 0,
                                       gg, (long)Ec * DFc, Nn, 8, 0);

    // stage 2: emb[b,n,e] = sum_d x[b,n,d] g[b,e,d] + emb1_b[e]
    tf32_gemm<<<dim3(16, Bc, 1), 256>>>(x, (long)Nn * DFc, 1, DFc, 1,
                                        gg, (long)Ec * DFc, Bc, DFc, 1,
                                        emb1_b, 0,
                                        gemb, (long)Nn * Ec, DFc, 1, 0);

    // stage 3: q, v projections per (b,h)
    tf32_gemm<<<dim3(16, Bc * Hc, 1), 256>>>(gemb, (long)Nn * Ec, Hc, Ec, 1,
                                             wq_W, (long)Ec * Ec, Hc, Ec, 1,
                                             wq_b, Ec,
                                             gq, (long)Nn * Ec, Ec, 1, 0);
    tf32_gemm<<<dim3(16, Bc * Hc, 1), 256>>>(gemb, (long)Nn * Ec, Hc, Ec, 1,
                                             wv_W, (long)Ec * Ec, Hc, Ec, 1,
                                             wv_b, Ec,
                                             gv, (long)Nn * Ec, Ec, 1, 0);

    // stage 4: u[b,h,d,f] = sum_n x[b,n,d] v[b,h,n,f]   (split-K 8, atomic)
    tf32_gemm<<<dim3(1, Bc * Hc, 8), 256>>>(x, (long)Nn * DFc, Hc, 1, DFc,
                                            gv, (long)Nn * Ec, Bc * Hc, 1, Ec,
                                            nullptr, 0,
                                            gu, (long)DFc * Ec, Nn, 8, 0);

    // stage 5: r[b,h,n,d] = sum_f q[b,h,n,f] u[b,h,d,f]
    tf32_gemm<<<dim3(16, Bc * Hc, 1), 256>>>(gq, (long)Nn * Ec, 1, Ec, 1,
                                             gu, (long)DFc * Ec, Bc * Hc, Ec, 1,
                                             nullptr, 0,
                                             gr, (long)Nn * DFc, Ec, 1, 0);

    // stage 6: fused attention (tensor cores)
    attn_mma_kernel<<<dim3(Nn / 128, Bc * Hc), 256, AT_SMEM_FLOATS * sizeof(float)>>>(
        gr, x, gv, gh);

    // stage 7: out = relu(hcat @ emb2_W^T + emb2_b)
    tf32_gemm<<<dim3(16, Bc, 1), 256>>>(gh, (long)Nn * Hc * Ec, 1, Hc * Ec, 1,
                                        emb2_W, 0, 1, Hc * Ec, 1,
                                        emb2_b, 0,
                                        out, (long)Nn * Ec, Hc * Ec, 1, 1);
}